// round 7
// baseline (speedup 1.0000x reference)
#include <cuda_runtime.h>

// AllReduce_77335181131889 — TP=4 sum + bias + residual + RMSNorm, fp32.
// R7: best-measured geometry (512 thr, 2 CTA/SM, default caching = R2) plus
// single-barrier reduction: warp partials -> one __syncthreads -> every
// thread sums 16 smem partials + computes rsqrt redundantly. Removes the
// second barrier, the warp-0 serial tree, and the scale broadcast.

#define T_DIM 8192
#define H_DIM 4096
#define H4    (H_DIM / 4)      // 1024 float4 per row
#define NTHREADS 512
#define VPT 2                  // float4 vectors per thread
#define NWARPS (NTHREADS / 32) // 16

__global__ __launch_bounds__(NTHREADS, 2)
void fused_ar_rmsnorm_kernel(const float4* __restrict__ x,      // [4*T*H4]
                             const float4* __restrict__ res,    // [T*H4]
                             const float4* __restrict__ bias,   // [H4]
                             const float4* __restrict__ w,      // [H4]
                             float4* __restrict__ norm_out,     // [T*H4]
                             float4* __restrict__ inter_out)    // [T*H4]
{
    const int row = blockIdx.x;
    const long rowOff = (long)row * H4;
    const long rs = (long)T_DIM * H4;   // rank stride in float4

    float4 inter[VPT];
    float ss = 0.0f;

    // Front-batched loads: 4 ranks + residual + bias per vector, x2 vectors.
    #pragma unroll
    for (int i = 0; i < VPT; i++) {
        const int col = threadIdx.x + i * NTHREADS;       // 0..1023
        const long p = rowOff + col;
        float4 a  = x[p];
        float4 b  = x[rs + p];
        float4 c  = x[2 * rs + p];
        float4 d  = x[3 * rs + p];
        float4 r  = res[p];
        float4 bi = bias[col];

        float4 v;
        v.x = ((a.x + b.x) + (c.x + d.x)) + (bi.x + r.x);
        v.y = ((a.y + b.y) + (c.y + d.y)) + (bi.y + r.y);
        v.z = ((a.z + b.z) + (c.z + d.z)) + (bi.z + r.z);
        v.w = ((a.w + b.w) + (c.w + d.w)) + (bi.w + r.w);

        ss = fmaf(v.x, v.x, ss);
        ss = fmaf(v.y, v.y, ss);
        ss = fmaf(v.z, v.z, ss);
        ss = fmaf(v.w, v.w, ss);

        inter[i] = v;
        inter_out[p] = v;   // stream intermediate out immediately
    }

    // Warp-level reduction of sum of squares.
    #pragma unroll
    for (int off = 16; off > 0; off >>= 1)
        ss += __shfl_xor_sync(0xFFFFFFFFu, ss, off);

    __shared__ float warp_ss[NWARPS];
    const int wid = threadIdx.x >> 5;
    const int lid = threadIdx.x & 31;
    if (lid == 0) warp_ss[wid] = ss;
    __syncthreads();

    // Single-barrier finish: every thread sums the 16 partials (broadcast
    // LDS, conflict-free) and computes its own scale. No second barrier.
    float s = 0.0f;
    #pragma unroll
    for (int i = 0; i < NWARPS; i++)
        s += warp_ss[i];
    const float scale = rsqrtf(s * (1.0f / (float)H_DIM) + 1e-6f);

    // Normalized output from register-resident inter.
    #pragma unroll
    for (int i = 0; i < VPT; i++) {
        const int col = threadIdx.x + i * NTHREADS;
        const long p = rowOff + col;
        float4 wt = w[col];
        float4 v = inter[i];
        float4 o;
        o.x = v.x * scale * wt.x;
        o.y = v.y * scale * wt.y;
        o.z = v.z * scale * wt.z;
        o.w = v.w * scale * wt.w;
        norm_out[p] = o;
    }
}

extern "C" void kernel_launch(void* const* d_in, const int* in_sizes, int n_in,
                              void* d_out, int out_size)
{
    const float4* x    = (const float4*)d_in[0];   // x_ranks [4,T,H]
    const float4* res  = (const float4*)d_in[1];   // residual [T,H]
    const float4* bias = (const float4*)d_in[2];   // bias [H]
    const float4* w    = (const float4*)d_in[3];   // norm_weight [H]

    float* out = (float*)d_out;
    float4* norm_out  = (float4*)out;                              // first T*H
    float4* inter_out = (float4*)(out + (long)T_DIM * H_DIM);      // second T*H

    fused_ar_rmsnorm_kernel<<<T_DIM, NTHREADS>>>(x, res, bias, w, norm_out, inter_out);
}

// round 8
// speedup vs baseline: 1.0122x; 1.0122x over previous
#include <cuda_runtime.h>

// AllReduce_77335181131889 — TP=4 sum + bias + residual + RMSNorm, fp32.
// R8: exact R2 structure (measured best: 127.3us, DRAM 89.2%) with one change:
// norm_weight loads hoisted into the front-batched load phase so their latency
// is hidden under the streaming reads instead of exposed on the post-barrier
// tail. launch_bounds(512,2) -> 64-reg budget, 2 CTAs/SM retained.

#define T_DIM 8192
#define H_DIM 4096
#define H4    (H_DIM / 4)      // 1024 float4 per row
#define NTHREADS 512
#define VPT 2                  // float4 vectors per thread

__global__ __launch_bounds__(NTHREADS, 2)
void fused_ar_rmsnorm_kernel(const float4* __restrict__ x,      // [4*T*H4]
                             const float4* __restrict__ res,    // [T*H4]
                             const float4* __restrict__ bias,   // [H4]
                             const float4* __restrict__ w,      // [H4]
                             float4* __restrict__ norm_out,     // [T*H4]
                             float4* __restrict__ inter_out)    // [T*H4]
{
    const int row = blockIdx.x;
    const long rowOff = (long)row * H4;
    const long rs = (long)T_DIM * H4;   // rank stride in float4

    float4 inter[VPT];
    float4 wt[VPT];
    float ss = 0.0f;

    // Front-batched loads: 4 ranks + residual + bias + WEIGHT per vector.
    #pragma unroll
    for (int i = 0; i < VPT; i++) {
        const int col = threadIdx.x + i * NTHREADS;       // 0..1023
        const long p = rowOff + col;
        float4 a  = x[p];
        float4 b  = x[rs + p];
        float4 c  = x[2 * rs + p];
        float4 d  = x[3 * rs + p];
        float4 r  = res[p];
        float4 bi = bias[col];
        wt[i]     = w[col];          // hoisted: hidden under streaming reads

        float4 v;
        v.x = ((a.x + b.x) + (c.x + d.x)) + (bi.x + r.x);
        v.y = ((a.y + b.y) + (c.y + d.y)) + (bi.y + r.y);
        v.z = ((a.z + b.z) + (c.z + d.z)) + (bi.z + r.z);
        v.w = ((a.w + b.w) + (c.w + d.w)) + (bi.w + r.w);

        ss = fmaf(v.x, v.x, ss);
        ss = fmaf(v.y, v.y, ss);
        ss = fmaf(v.z, v.z, ss);
        ss = fmaf(v.w, v.w, ss);

        inter[i] = v;
        inter_out[p] = v;   // stream intermediate out immediately
    }

    // Block reduction of sum of squares (R2 scheme — measured best).
    #pragma unroll
    for (int off = 16; off > 0; off >>= 1)
        ss += __shfl_xor_sync(0xFFFFFFFFu, ss, off);

    __shared__ float warp_ss[NTHREADS / 32];
    __shared__ float scale_sh;
    const int wid = threadIdx.x >> 5;
    const int lid = threadIdx.x & 31;
    if (lid == 0) warp_ss[wid] = ss;
    __syncthreads();

    if (wid == 0) {
        float s = (lid < NTHREADS / 32) ? warp_ss[lid] : 0.0f;
        #pragma unroll
        for (int off = 8; off > 0; off >>= 1)
            s += __shfl_xor_sync(0xFFFFFFFFu, s, off);
        if (lid == 0)
            scale_sh = rsqrtf(s * (1.0f / (float)H_DIM) + 1e-6f);
    }
    __syncthreads();
    const float scale = scale_sh;

    // Tail: pure register math + stores (weights already resident).
    #pragma unroll
    for (int i = 0; i < VPT; i++) {
        const int col = threadIdx.x + i * NTHREADS;
        const long p = rowOff + col;
        float4 v = inter[i];
        float4 o;
        o.x = v.x * scale * wt[i].x;
        o.y = v.y * scale * wt[i].y;
        o.z = v.z * scale * wt[i].z;
        o.w = v.w * scale * wt[i].w;
        norm_out[p] = o;
    }
}

extern "C" void kernel_launch(void* const* d_in, const int* in_sizes, int n_in,
                              void* d_out, int out_size)
{
    const float4* x    = (const float4*)d_in[0];   // x_ranks [4,T,H]
    const float4* res  = (const float4*)d_in[1];   // residual [T,H]
    const float4* bias = (const float4*)d_in[2];   // bias [H]
    const float4* w    = (const float4*)d_in[3];   // norm_weight [H]

    float* out = (float*)d_out;
    float4* norm_out  = (float4*)out;                              // first T*H
    float4* inter_out = (float4*)(out + (long)T_DIM * H_DIM);      // second T*H

    fused_ar_rmsnorm_kernel<<<T_DIM, NTHREADS>>>(x, res, bias, w, norm_out, inter_out);
}